// round 1
// baseline (speedup 1.0000x reference)
#include <cuda_runtime.h>

// ---------------- problem constants ----------------
#define KSNAP 8
#define NNODE 10000
#define NEDGE 160000
#define EPTOT (NEDGE + NNODE)   // edges + self loops = 170000
#define HEADS 8
#define D2 256                  // HEADS*32
#define LH 256
#define NEG 0.2f

// ---------------- static scratch (no allocation allowed) ----------------
static __device__ float g_feat[KSNAP * NNODE * D2];     // pre-agg features of current layer
static __device__ float g_buf [KSNAP * NNODE * D2];     // post-agg (relu) output of current layer
static __device__ float g_ssrc[KSNAP * NNODE * HEADS];
static __device__ float g_sdst[KSNAP * NNODE * HEADS];
static __device__ int   g_deg [KSNAP * NNODE];
static __device__ int   g_off [KSNAP * (NNODE + 1)];
static __device__ int   g_pos [KSNAP * NNODE];
static __device__ int   g_adj [KSNAP * EPTOT];          // src node per CSR slot (dst implicit)
static __device__ float g_emb [KSNAP * D2];             // pooled embeddings
static __device__ float g_xw  [2 * KSNAP * 4 * LH];     // precomputed embs @ Wih^T  [dir][k][gate]
static __device__ float g_whhT[2 * LH * 4 * LH];        // transposed Whh  [dir][j][gate]

// ---------------- helpers ----------------
__device__ __forceinline__ float warp_sum(float v) {
#pragma unroll
    for (int o = 16; o; o >>= 1) v += __shfl_xor_sync(0xffffffffu, v, o);
    return v;
}

// ---------------- CSR build ----------------
__global__ void k_zero() {
    int i = blockIdx.x * blockDim.x + threadIdx.x;
    if (i < KSNAP * NNODE) g_deg[i] = 0;
    if (i < KSNAP * D2)    g_emb[i] = 0.f;
}

__global__ void k_count(const int* __restrict__ ei) {
    int idx = blockIdx.x * blockDim.x + threadIdx.x;
    if (idx >= KSNAP * EPTOT) return;
    int k = idx / EPTOT, e = idx % EPTOT;
    int dst = (e < NEDGE) ? ei[(k * 2 + 1) * NEDGE + e] : (e - NEDGE);
    atomicAdd(&g_deg[k * NNODE + dst], 1);
}

__global__ void k_scan() {
    // one block per snapshot; 1024 threads, 10 elems each
    __shared__ int part[1024];
    int k = blockIdx.x, t = threadIdx.x;
    int base = t * 10;
    int loc[10];
    int s = 0;
#pragma unroll
    for (int i = 0; i < 10; i++) {
        int n = base + i;
        int v = (n < NNODE) ? g_deg[k * NNODE + n] : 0;
        loc[i] = s; s += v;
    }
    part[t] = s;
    __syncthreads();
    for (int ofs = 1; ofs < 1024; ofs <<= 1) {
        int v = (t >= ofs) ? part[t - ofs] : 0;
        __syncthreads();
        part[t] += v;
        __syncthreads();
    }
    int pre = (t == 0) ? 0 : part[t - 1];
#pragma unroll
    for (int i = 0; i < 10; i++) {
        int n = base + i;
        if (n < NNODE) {
            int o = pre + loc[i];
            g_off[k * (NNODE + 1) + n] = o;
            g_pos[k * NNODE + n]       = o;
        }
    }
    if (t == 1023) g_off[k * (NNODE + 1) + NNODE] = part[1023];
}

__global__ void k_scatter(const int* __restrict__ ei) {
    int idx = blockIdx.x * blockDim.x + threadIdx.x;
    if (idx >= KSNAP * EPTOT) return;
    int k = idx / EPTOT, e = idx % EPTOT;
    int src, dst;
    if (e < NEDGE) {
        src = ei[(k * 2 + 0) * NEDGE + e];
        dst = ei[(k * 2 + 1) * NEDGE + e];
    } else {
        src = e - NEDGE;
        dst = e - NEDGE;
    }
    int slot = atomicAdd(&g_pos[k * NNODE + dst], 1);
    g_adj[k * EPTOT + slot] = src;
}

// ---------------- layer 1 feature transform (Din = 1) + attention s-vectors ----------------
__global__ void k_l1(const float* __restrict__ xs, const float* __restrict__ W1,
                     const float* __restrict__ a_src, const float* __restrict__ a_dst) {
    int n = blockIdx.x, k = blockIdx.y, c = threadIdx.x;
    long node = (long)k * NNODE + n;
    float x = xs[node];                 // xs is (K,N,1)
    float v = x * W1[c];
    g_feat[node * D2 + c] = v;
    float vs = warp_sum(v * a_src[c]);
    float vd = warp_sum(v * a_dst[c]);
    int w = c >> 5;
    if ((c & 31) == 0) {
        g_ssrc[node * HEADS + w] = vs;
        g_sdst[node * HEADS + w] = vd;
    }
}

// ---------------- s-vectors for layer 2 (features already in g_feat) ----------------
__global__ void k_sheads(const float* __restrict__ a_src, const float* __restrict__ a_dst) {
    int n = blockIdx.x, k = blockIdx.y, c = threadIdx.x;
    long node = (long)k * NNODE + n;
    float v = g_feat[node * D2 + c];
    float vs = warp_sum(v * a_src[c]);
    float vd = warp_sum(v * a_dst[c]);
    int w = c >> 5;
    if ((c & 31) == 0) {
        g_ssrc[node * HEADS + w] = vs;
        g_sdst[node * HEADS + w] = vd;
    }
}

// ---------------- GAT aggregation: warp per destination node ----------------
__global__ __launch_bounds__(256) void k_agg(const float* __restrict__ bias) {
    int k = blockIdx.y;
    int n = blockIdx.x * 8 + (threadIdx.x >> 5);
    if (n >= NNODE) return;
    int lane = threadIdx.x & 31;
    long base = (long)k * NNODE;
    int o0 = g_off[k * (NNODE + 1) + n];
    int o1 = g_off[k * (NNODE + 1) + n + 1];
    const int* adj = g_adj + (long)k * EPTOT;

    float sd[HEADS];
#pragma unroll
    for (int i = 0; i < HEADS; i++) sd[i] = g_sdst[(base + n) * HEADS + i];

    // pass 1: per-head max over incoming edges
    float m[HEADS];
#pragma unroll
    for (int i = 0; i < HEADS; i++) m[i] = -1e30f;
    for (int j = o0 + lane; j < o1; j += 32) {
        int s = adj[j];
        const float* sp = &g_ssrc[(base + s) * HEADS];
#pragma unroll
        for (int i = 0; i < HEADS; i++) {
            float e = sp[i] + sd[i];
            e = (e >= 0.f) ? e : NEG * e;
            m[i] = fmaxf(m[i], e);
        }
    }
#pragma unroll
    for (int i = 0; i < HEADS; i++)
#pragma unroll
        for (int o = 16; o; o >>= 1) m[i] = fmaxf(m[i], __shfl_xor_sync(0xffffffffu, m[i], o));

    // pass 2: denominators
    float dsum[HEADS];
#pragma unroll
    for (int i = 0; i < HEADS; i++) dsum[i] = 0.f;
    for (int j = o0 + lane; j < o1; j += 32) {
        int s = adj[j];
        const float* sp = &g_ssrc[(base + s) * HEADS];
#pragma unroll
        for (int i = 0; i < HEADS; i++) {
            float e = sp[i] + sd[i];
            e = (e >= 0.f) ? e : NEG * e;
            dsum[i] += __expf(e - m[i]);
        }
    }
    float inv[HEADS];
#pragma unroll
    for (int i = 0; i < HEADS; i++) inv[i] = 1.f / (warp_sum(dsum[i]) + 1e-16f);

    // pass 3: weighted gather-accumulate, lane owns channel (32*i + lane)
    float acc[HEADS];
#pragma unroll
    for (int i = 0; i < HEADS; i++) acc[i] = 0.f;
    int il = lane & 7;
    float sd_l = sd[il], m_l = m[il], inv_l = inv[il];
    for (int j = o0; j < o1; j++) {
        int s = adj[j];
        float e = g_ssrc[(base + s) * HEADS + il] + sd_l;
        e = (e >= 0.f) ? e : NEG * e;
        float a = __expf(e - m_l) * inv_l;
        const float* fp = &g_feat[(base + s) * D2];
#pragma unroll
        for (int i = 0; i < HEADS; i++) {
            float al = __shfl_sync(0xffffffffu, a, i);
            acc[i] += fp[i * 32 + lane] * al;
        }
    }
    float* op = &g_buf[(base + n) * D2];
#pragma unroll
    for (int i = 0; i < HEADS; i++) {
        float v = acc[i] + bias[i * 32 + lane];
        op[i * 32 + lane] = fmaxf(v, 0.f);   // relu after each GAT layer
    }
}

// ---------------- SGEMM: g_buf(80000x256) @ W2(256x256) -> g_feat ----------------
#define BM 128
#define BN 128
#define BKK 16
__global__ __launch_bounds__(256) void k_gemm(const float* __restrict__ B) {
    __shared__ float As[BKK][BM];
    __shared__ float Bs[BKK][BN];
    const float* A = g_buf;
    float* C = g_feat;
    int m0 = blockIdx.x * BM;
    int n0 = blockIdx.y * BN;
    int tid = threadIdx.x;
    int tx = tid & 15, ty = tid >> 4;
    float acc[8][8];
#pragma unroll
    for (int r = 0; r < 8; r++)
#pragma unroll
        for (int c = 0; c < 8; c++) acc[r][c] = 0.f;

    for (int kt = 0; kt < D2; kt += BKK) {
#pragma unroll
        for (int q = 0; q < 2; q++) {
            int id = tid + q * 256;
            int ar = id >> 2, akq = id & 3;
            float4 v = *(const float4*)&A[(long)(m0 + ar) * D2 + kt + akq * 4];
            As[akq * 4 + 0][ar] = v.x;
            As[akq * 4 + 1][ar] = v.y;
            As[akq * 4 + 2][ar] = v.z;
            As[akq * 4 + 3][ar] = v.w;
            int br = id >> 5, bq = id & 31;
            *(float4*)&Bs[br][bq * 4] = *(const float4*)&B[(long)(kt + br) * D2 + n0 + bq * 4];
        }
        __syncthreads();
#pragma unroll
        for (int kk = 0; kk < BKK; kk++) {
            float a[8], b[8];
            *(float4*)&a[0] = *(const float4*)&As[kk][ty * 8];
            *(float4*)&a[4] = *(const float4*)&As[kk][ty * 8 + 4];
            *(float4*)&b[0] = *(const float4*)&Bs[kk][tx * 8];
            *(float4*)&b[4] = *(const float4*)&Bs[kk][tx * 8 + 4];
#pragma unroll
            for (int r = 0; r < 8; r++)
#pragma unroll
                for (int c = 0; c < 8; c++) acc[r][c] = fmaf(a[r], b[c], acc[r][c]);
        }
        __syncthreads();
    }
#pragma unroll
    for (int r = 0; r < 8; r++) {
#pragma unroll
        for (int cq = 0; cq < 2; cq++) {
            float4 v = make_float4(acc[r][cq * 4], acc[r][cq * 4 + 1], acc[r][cq * 4 + 2], acc[r][cq * 4 + 3]);
            *(float4*)&C[(long)(m0 + ty * 8 + r) * D2 + n0 + tx * 8 + cq * 4] = v;
        }
    }
}

// ---------------- global mean pool ----------------
__global__ void k_pool() {
    int k = blockIdx.y, c = threadIdx.x;
    float s = 0.f;
    for (int n = blockIdx.x; n < NNODE; n += gridDim.x)
        s += g_buf[((long)k * NNODE + n) * D2 + c];
    atomicAdd(&g_emb[k * D2 + c], s * (1.0f / NNODE));
}

// ---------------- LSTM input projections: embs @ Wih^T ----------------
__global__ void k_xw(const float* __restrict__ Wih_f, const float* __restrict__ Wih_b) {
    int gid = blockIdx.x * 8 + (threadIdx.x >> 5);     // 0 .. 16383
    int lane = threadIdx.x & 31;
    int d = gid >> 13;
    int rem = gid & 8191;
    int k = rem >> 10;
    int g = rem & 1023;
    const float* Wih = d ? Wih_b : Wih_f;
    float s = 0.f;
    for (int j = lane; j < D2; j += 32)
        s += Wih[g * D2 + j] * g_emb[k * D2 + j];
    s = warp_sum(s);
    if (lane == 0) g_xw[gid] = s;
}

__global__ void k_whhT(const float* __restrict__ Whh_f, const float* __restrict__ Whh_b) {
    int idx = blockIdx.x * blockDim.x + threadIdx.x;
    if (idx >= 2 * 1024 * 256) return;
    int d = idx >> 18;
    int r = idx & ((1 << 18) - 1);
    int g = r >> 8;          // 0..1023
    int j = r & 255;         // 0..255
    const float* W = d ? Whh_b : Whh_f;
    g_whhT[((long)d * 256 + j) * 1024 + g] = W[g * 256 + j];
}

// ---------------- bidirectional LSTM (2 blocks, 8 sequential steps each) ----------------
__global__ __launch_bounds__(1024) void k_lstm(const float* __restrict__ bih_f, const float* __restrict__ bhh_f,
                                               const float* __restrict__ bih_b, const float* __restrict__ bhh_b,
                                               float* __restrict__ out) {
    int d = blockIdx.x;
    int t = threadIdx.x;
    __shared__ float h[LH], cc[LH], gbuf[4 * LH];
    if (t < LH) { h[t] = 0.f; cc[t] = 0.f; }
    const float* bih = d ? bih_b : bih_f;
    const float* bhh = d ? bhh_b : bhh_f;
    const float* WT = g_whhT + (long)d * LH * 4 * LH;
    float bsum = bih[t] + bhh[t];
    __syncthreads();
    for (int step = 0; step < KSNAP; step++) {
        int kk = d ? (KSNAP - 1 - step) : step;
        float acc = g_xw[((long)d * KSNAP + kk) * 1024 + t] + bsum;
#pragma unroll 8
        for (int j = 0; j < LH; j++)
            acc = fmaf(WT[(long)j * 1024 + t], h[j], acc);
        gbuf[t] = acc;
        __syncthreads();
        if (t < LH) {
            float ig = 1.f / (1.f + expf(-gbuf[t]));
            float fg = 1.f / (1.f + expf(-gbuf[LH + t]));
            float gg = tanhf(gbuf[2 * LH + t]);
            float og = 1.f / (1.f + expf(-gbuf[3 * LH + t]));
            float cn = fg * cc[t] + ig * gg;
            cc[t] = cn;
            h[t] = og * tanhf(cn);
        }
        __syncthreads();
    }
    if (t < LH) out[d * LH + t] = h[t];
}

// ---------------- launch ----------------
extern "C" void kernel_launch(void* const* d_in, const int* in_sizes, int n_in,
                              void* d_out, int out_size) {
    const float* xs     = (const float*)d_in[0];
    const int*   ei     = (const int*)  d_in[1];
    const float* W1     = (const float*)d_in[2];
    const float* a_src1 = (const float*)d_in[3];
    const float* a_dst1 = (const float*)d_in[4];
    const float* b1     = (const float*)d_in[5];
    const float* W2     = (const float*)d_in[6];
    const float* a_src2 = (const float*)d_in[7];
    const float* a_dst2 = (const float*)d_in[8];
    const float* b2     = (const float*)d_in[9];
    const float* Wih_f  = (const float*)d_in[10];
    const float* Whh_f  = (const float*)d_in[11];
    const float* bih_f  = (const float*)d_in[12];
    const float* bhh_f  = (const float*)d_in[13];
    const float* Wih_b  = (const float*)d_in[14];
    const float* Whh_b  = (const float*)d_in[15];
    const float* bih_b  = (const float*)d_in[16];
    const float* bhh_b  = (const float*)d_in[17];
    float* out = (float*)d_out;

    // CSR build (all snapshots batched)
    {
        int total = KSNAP * NNODE;  // >= KSNAP*D2
        k_zero<<<(total + 255) / 256, 256>>>();
    }
    k_count<<<(KSNAP * EPTOT + 255) / 256, 256>>>(ei);
    k_scan<<<KSNAP, 1024>>>();
    k_scatter<<<(KSNAP * EPTOT + 255) / 256, 256>>>(ei);

    dim3 gnode(NNODE, KSNAP);
    dim3 gagg((NNODE + 7) / 8, KSNAP);

    // layer 1
    k_l1<<<gnode, 256>>>(xs, W1, a_src1, a_dst1);
    k_agg<<<gagg, 256>>>(b1);                      // g_feat -> g_buf (relu h1)

    // layer 2
    k_gemm<<<dim3((KSNAP * NNODE) / BM, D2 / BN), 256>>>(W2);   // g_buf -> g_feat
    k_sheads<<<gnode, 256>>>(a_src2, a_dst2);
    k_agg<<<gagg, 256>>>(b2);                      // g_feat -> g_buf (relu h2)

    // mean pool
    k_pool<<<dim3(32, KSNAP), 256>>>();

    // LSTM
    k_whhT<<<(2 * 1024 * 256 + 255) / 256, 256>>>(Whh_f, Whh_b);
    k_xw<<<2048, 256>>>(Wih_f, Wih_b);
    k_lstm<<<2, 1024>>>(bih_f, bhh_f, bih_b, bhh_b, out);
}

// round 2
// speedup vs baseline: 1.2665x; 1.2665x over previous
#include <cuda_runtime.h>

// ---------------- problem constants ----------------
#define KSNAP 8
#define NNODE 10000
#define NEDGE 160000
#define EPTOT (NEDGE + NNODE)   // edges + self loops = 170000
#define HEADS 8
#define D2 256                  // HEADS*32
#define LH 256
#define NEG 0.2f

// ---------------- static scratch ----------------
static __device__ float g_feat[KSNAP * NNODE * D2];     // layer-2 linear output (gather source)
static __device__ float g_buf [KSNAP * NNODE * D2];     // layer-2 GAT output (pool source)
static __device__ float g_t   [KSNAP * NNODE * HEADS];  // layer-1 aggregated scalars per head
static __device__ float g_ssrc[KSNAP * NNODE * HEADS];
static __device__ float g_sdst[KSNAP * NNODE * HEADS];
static __device__ float g_q   [2 * HEADS];              // qs[8], qd[8]
static __device__ int   g_deg [KSNAP * NNODE];
static __device__ int   g_off [KSNAP * (NNODE + 1)];
static __device__ int   g_pos [KSNAP * NNODE];
static __device__ int   g_adj [KSNAP * EPTOT];
static __device__ float g_emb [KSNAP * D2];
static __device__ float g_xw  [2 * KSNAP * 4 * LH];
static __device__ float2 g_whhT2[2 * 128 * 1024];       // [dir][j2][gate] packed pairs over j

// ---------------- helpers ----------------
__device__ __forceinline__ float warp_sum(float v) {
#pragma unroll
    for (int o = 16; o; o >>= 1) v += __shfl_xor_sync(0xffffffffu, v, o);
    return v;
}
__device__ __forceinline__ float warp_max(float v) {
#pragma unroll
    for (int o = 16; o; o >>= 1) v = fmaxf(v, __shfl_xor_sync(0xffffffffu, v, o));
    return v;
}
#define FMA2(d, a, b) asm("fma.rn.f32x2 %0, %1, %2, %0;" : "+l"(d) : "l"(a), "l"(b))
__device__ __forceinline__ void unpack2(unsigned long long v, float& lo, float& hi) {
    unsigned int l = (unsigned int)(v & 0xffffffffull);
    unsigned int h = (unsigned int)(v >> 32);
    lo = __uint_as_float(l); hi = __uint_as_float(h);
}

// ---------------- CSR build ----------------
__global__ void k_zero() {
    int i = blockIdx.x * blockDim.x + threadIdx.x;
    if (i < KSNAP * NNODE) g_deg[i] = 0;
    if (i < KSNAP * D2)    g_emb[i] = 0.f;
}

__global__ void k_count(const int* __restrict__ ei) {
    int idx = blockIdx.x * blockDim.x + threadIdx.x;
    if (idx >= KSNAP * EPTOT) return;
    int k = idx / EPTOT, e = idx % EPTOT;
    int dst = (e < NEDGE) ? ei[(k * 2 + 1) * NEDGE + e] : (e - NEDGE);
    atomicAdd(&g_deg[k * NNODE + dst], 1);
}

__global__ void k_scan() {
    __shared__ int part[1024];
    int k = blockIdx.x, t = threadIdx.x;
    int base = t * 10;
    int loc[10];
    int s = 0;
#pragma unroll
    for (int i = 0; i < 10; i++) {
        int n = base + i;
        int v = (n < NNODE) ? g_deg[k * NNODE + n] : 0;
        loc[i] = s; s += v;
    }
    part[t] = s;
    __syncthreads();
    for (int ofs = 1; ofs < 1024; ofs <<= 1) {
        int v = (t >= ofs) ? part[t - ofs] : 0;
        __syncthreads();
        part[t] += v;
        __syncthreads();
    }
    int pre = (t == 0) ? 0 : part[t - 1];
#pragma unroll
    for (int i = 0; i < 10; i++) {
        int n = base + i;
        if (n < NNODE) {
            int o = pre + loc[i];
            g_off[k * (NNODE + 1) + n] = o;
            g_pos[k * NNODE + n]       = o;
        }
    }
    if (t == 1023) g_off[k * (NNODE + 1) + NNODE] = part[1023];
}

__global__ void k_scatter(const int* __restrict__ ei) {
    int idx = blockIdx.x * blockDim.x + threadIdx.x;
    if (idx >= KSNAP * EPTOT) return;
    int k = idx / EPTOT, e = idx % EPTOT;
    int src, dst;
    if (e < NEDGE) {
        src = ei[(k * 2 + 0) * NEDGE + e];
        dst = ei[(k * 2 + 1) * NEDGE + e];
    } else {
        src = e - NEDGE;
        dst = e - NEDGE;
    }
    int slot = atomicAdd(&g_pos[k * NNODE + dst], 1);
    g_adj[k * EPTOT + slot] = src;
}

// ---------------- layer-1 prep: q vectors ----------------
__global__ void k_prep(const float* __restrict__ W1, const float* __restrict__ as1,
                       const float* __restrict__ ad1) {
    int c = threadIdx.x;   // 256
    float w = W1[c];
    float vs = warp_sum(w * as1[c]);
    float vd = warp_sum(w * ad1[c]);
    if ((c & 31) == 0) {
        g_q[c >> 5] = vs;
        g_q[8 + (c >> 5)] = vd;
    }
}

// ---------------- layer-1 GAT, fully scalar (Din=1 algebraic collapse) ----------------
__global__ __launch_bounds__(256) void k_agg1(const float* __restrict__ xs) {
    int k = blockIdx.y;
    int n = blockIdx.x * 8 + (threadIdx.x >> 5);
    int lane = threadIdx.x & 31;
    long base = (long)k * NNODE;
    int o0 = g_off[k * (NNODE + 1) + n];
    int o1 = g_off[k * (NNODE + 1) + n + 1];
    const int* adj = g_adj + (long)k * EPTOT;

    float qs[HEADS], qd[HEADS], dterm[HEADS];
    float xd = xs[base + n];
#pragma unroll
    for (int i = 0; i < HEADS; i++) { qs[i] = g_q[i]; qd[i] = g_q[8 + i]; dterm[i] = xd * qd[i]; }

    // online softmax stats per lane per head
    float m[HEADS], sm[HEADS];
#pragma unroll
    for (int i = 0; i < HEADS; i++) { m[i] = -1e30f; sm[i] = 0.f; }
    for (int j = o0 + lane; j < o1; j += 32) {
        int s = adj[j];
        float xv = xs[base + s];
#pragma unroll
        for (int i = 0; i < HEADS; i++) {
            float e = fmaf(xv, qs[i], dterm[i]);
            e = (e >= 0.f) ? e : NEG * e;
            float mn = fmaxf(m[i], e);
            sm[i] = sm[i] * __expf(m[i] - mn) + __expf(e - mn);
            m[i] = mn;
        }
    }
    float inv[HEADS];
#pragma unroll
    for (int i = 0; i < HEADS; i++) {
        float mg = warp_max(m[i]);
        float c = warp_sum(sm[i] * __expf(m[i] - mg));
        inv[i] = 1.f / (c + 1e-16f);
        m[i] = mg;
    }
    float t[HEADS];
#pragma unroll
    for (int i = 0; i < HEADS; i++) t[i] = 0.f;
    for (int j = o0 + lane; j < o1; j += 32) {
        int s = adj[j];
        float xv = xs[base + s];
#pragma unroll
        for (int i = 0; i < HEADS; i++) {
            float e = fmaf(xv, qs[i], dterm[i]);
            e = (e >= 0.f) ? e : NEG * e;
            t[i] = fmaf(__expf(e - m[i]), xv, t[i]);
        }
    }
#pragma unroll
    for (int i = 0; i < HEADS; i++) {
        float tv = warp_sum(t[i]);
        if (lane == 0) g_t[(base + n) * HEADS + i] = tv * inv[i];
    }
}

// ---------------- fused GEMM: A = relu(outer(t,W1)+b1) built on-the-fly; f32x2 MACs ----------------
// C = A @ W2 -> g_feat ; epilogue computes layer-2 s-vectors
#define BM 128
#define BN 128
#define BKK 16
__global__ __launch_bounds__(256) void k_gemm(const float* __restrict__ W2,
                                              const float* __restrict__ W1,
                                              const float* __restrict__ b1,
                                              const float* __restrict__ as2,
                                              const float* __restrict__ ad2) {
    __shared__ float t_sh[BM][8];
    __shared__ float As[BKK][2 * BM];   // duplicated pairs: As[k][2m]=As[k][2m+1]=A[m][k]
    __shared__ float Bs[BKK][BN];
    int m0 = blockIdx.x * BM;
    int n0 = blockIdx.y * BN;
    int tid = threadIdx.x;
    int tx = tid & 15, ty = tid >> 4;

    {   // load t rows for this block
        int row = tid >> 1, part = tid & 1;
        *(float4*)&t_sh[row][part * 4] = *(const float4*)&g_t[((long)(m0 + row)) * 8 + part * 4];
    }
    __syncthreads();

    unsigned long long acc2[8][4];
#pragma unroll
    for (int r = 0; r < 8; r++)
#pragma unroll
        for (int p = 0; p < 4; p++) acc2[r][p] = 0ull;

    for (int kt = 0; kt < D2; kt += BKK) {
        // Bs fill
#pragma unroll
        for (int q = 0; q < 2; q++) {
            int id = tid + q * 256;
            int br = id >> 5, bq = id & 31;
            *(float4*)&Bs[br][bq * 4] = *(const float4*)&W2[(long)(kt + br) * D2 + n0 + bq * 4];
        }
        // As fill from t (head constant across this 16-wide k tile)
        int head = kt >> 5;
#pragma unroll
        for (int q = 0; q < 8; q++) {
            int id = tid + q * 256;
            int kk = id & 15, mm = id >> 4;
            float v = fmaf(W1[kt + kk], t_sh[mm][head], b1[kt + kk]);
            v = fmaxf(v, 0.f);
            *(float2*)&As[kk][2 * mm] = make_float2(v, v);
        }
        __syncthreads();
#pragma unroll
        for (int kk = 0; kk < BKK; kk++) {
            ulonglong2 a01 = *(const ulonglong2*)&As[kk][ty * 16];
            ulonglong2 a23 = *(const ulonglong2*)&As[kk][ty * 16 + 4];
            ulonglong2 a45 = *(const ulonglong2*)&As[kk][ty * 16 + 8];
            ulonglong2 a67 = *(const ulonglong2*)&As[kk][ty * 16 + 12];
            ulonglong2 b01 = *(const ulonglong2*)&Bs[kk][tx * 8];
            ulonglong2 b23 = *(const ulonglong2*)&Bs[kk][tx * 8 + 4];
            unsigned long long av[8] = {a01.x, a01.y, a23.x, a23.y, a45.x, a45.y, a67.x, a67.y};
            unsigned long long bv[4] = {b01.x, b01.y, b23.x, b23.y};
#pragma unroll
            for (int r = 0; r < 8; r++)
#pragma unroll
                for (int p = 0; p < 4; p++) FMA2(acc2[r][p], av[r], bv[p]);
        }
        __syncthreads();
    }

    // unpack
    float accf[8][8];
#pragma unroll
    for (int r = 0; r < 8; r++)
#pragma unroll
        for (int p = 0; p < 4; p++) unpack2(acc2[r][p], accf[r][2 * p], accf[r][2 * p + 1]);

    // store C
#pragma unroll
    for (int r = 0; r < 8; r++) {
        long row = m0 + ty * 8 + r;
        *(float4*)&g_feat[row * D2 + n0 + tx * 8]     = make_float4(accf[r][0], accf[r][1], accf[r][2], accf[r][3]);
        *(float4*)&g_feat[row * D2 + n0 + tx * 8 + 4] = make_float4(accf[r][4], accf[r][5], accf[r][6], accf[r][7]);
    }

    // epilogue: layer-2 attention s-vectors (exact; 4-lane groups own one head)
    float avs[8], avd[8];
#pragma unroll
    for (int q = 0; q < 8; q++) {
        avs[q] = as2[n0 + tx * 8 + q];
        avd[q] = ad2[n0 + tx * 8 + q];
    }
    int head = (n0 >> 5) + (tx >> 2);
#pragma unroll
    for (int r = 0; r < 8; r++) {
        float ss = 0.f, sd = 0.f;
#pragma unroll
        for (int q = 0; q < 8; q++) {
            ss = fmaf(accf[r][q], avs[q], ss);
            sd = fmaf(accf[r][q], avd[q], sd);
        }
        ss += __shfl_xor_sync(0xffffffffu, ss, 1);
        ss += __shfl_xor_sync(0xffffffffu, ss, 2);
        sd += __shfl_xor_sync(0xffffffffu, sd, 1);
        sd += __shfl_xor_sync(0xffffffffu, sd, 2);
        if ((tx & 3) == 0) {
            long row = m0 + ty * 8 + r;
            g_ssrc[row * HEADS + head] = ss;
            g_sdst[row * HEADS + head] = sd;
        }
    }
}

// ---------------- layer-2 GAT aggregation: online softmax + float4 gather ----------------
__global__ __launch_bounds__(256) void k_agg2(const float* __restrict__ bias) {
    __shared__ float s_m[8][8], s_inv[8][8], s_sd[8][8];
    int k = blockIdx.y;
    int w = threadIdx.x >> 5;
    int n = blockIdx.x * 8 + w;
    int lane = threadIdx.x & 31;
    long base = (long)k * NNODE;
    int o0 = g_off[k * (NNODE + 1) + n];
    int o1 = g_off[k * (NNODE + 1) + n + 1];
    const int* adj = g_adj + (long)k * EPTOT;

    float sd[HEADS];
    {
        float4 d0 = *(const float4*)&g_sdst[(base + n) * HEADS];
        float4 d1 = *(const float4*)&g_sdst[(base + n) * HEADS + 4];
        sd[0] = d0.x; sd[1] = d0.y; sd[2] = d0.z; sd[3] = d0.w;
        sd[4] = d1.x; sd[5] = d1.y; sd[6] = d1.z; sd[7] = d1.w;
    }

    float m[HEADS], sm[HEADS];
#pragma unroll
    for (int i = 0; i < HEADS; i++) { m[i] = -1e30f; sm[i] = 0.f; }
    for (int j = o0 + lane; j < o1; j += 32) {
        int s = adj[j];
        const float4* sp = (const float4*)&g_ssrc[(base + s) * HEADS];
        float4 s0 = sp[0], s1 = sp[1];
        float sv[8] = {s0.x, s0.y, s0.z, s0.w, s1.x, s1.y, s1.z, s1.w};
#pragma unroll
        for (int i = 0; i < HEADS; i++) {
            float e = sv[i] + sd[i];
            e = (e >= 0.f) ? e : NEG * e;
            float mn = fmaxf(m[i], e);
            sm[i] = sm[i] * __expf(m[i] - mn) + __expf(e - mn);
            m[i] = mn;
        }
    }
    float inv[HEADS];
#pragma unroll
    for (int i = 0; i < HEADS; i++) {
        float mg = warp_max(m[i]);
        float c = warp_sum(sm[i] * __expf(m[i] - mg));
        inv[i] = 1.f / (c + 1e-16f);
        m[i] = mg;
    }
    if (lane == 0) {
#pragma unroll
        for (int i = 0; i < HEADS; i++) {
            s_m[w][i] = m[i]; s_inv[w][i] = inv[i]; s_sd[w][i] = sd[i];
        }
    }
    __syncwarp();
    int hl = lane >> 2;                 // head owned by this lane (channels lane*8 .. +7)
    float m_l = s_m[w][hl], inv_l = s_inv[w][hl], sd_l = s_sd[w][hl];

    float4 a0 = make_float4(0.f, 0.f, 0.f, 0.f);
    float4 a1 = make_float4(0.f, 0.f, 0.f, 0.f);
    for (int j = o0; j < o1; j++) {
        int s = adj[j];
        float ss = g_ssrc[(base + s) * HEADS + hl];
        float e = ss + sd_l;
        e = (e >= 0.f) ? e : NEG * e;
        float al = __expf(e - m_l) * inv_l;
        const float4* fp = (const float4*)&g_feat[(base + s) * D2 + lane * 8];
        float4 f0 = fp[0], f1 = fp[1];
        a0.x = fmaf(f0.x, al, a0.x); a0.y = fmaf(f0.y, al, a0.y);
        a0.z = fmaf(f0.z, al, a0.z); a0.w = fmaf(f0.w, al, a0.w);
        a1.x = fmaf(f1.x, al, a1.x); a1.y = fmaf(f1.y, al, a1.y);
        a1.z = fmaf(f1.z, al, a1.z); a1.w = fmaf(f1.w, al, a1.w);
    }
    float4 b0 = *(const float4*)&bias[lane * 8];
    float4 b1v = *(const float4*)&bias[lane * 8 + 4];
    float4 o0v = make_float4(fmaxf(a0.x + b0.x, 0.f), fmaxf(a0.y + b0.y, 0.f),
                             fmaxf(a0.z + b0.z, 0.f), fmaxf(a0.w + b0.w, 0.f));
    float4 o1v = make_float4(fmaxf(a1.x + b1v.x, 0.f), fmaxf(a1.y + b1v.y, 0.f),
                             fmaxf(a1.z + b1v.z, 0.f), fmaxf(a1.w + b1v.w, 0.f));
    *(float4*)&g_buf[(base + n) * D2 + lane * 8]     = o0v;
    *(float4*)&g_buf[(base + n) * D2 + lane * 8 + 4] = o1v;
}

// ---------------- global mean pool ----------------
__global__ void k_pool() {
    int k = blockIdx.y, c = threadIdx.x;
    float s = 0.f;
    for (int n = blockIdx.x; n < NNODE; n += gridDim.x)
        s += g_buf[((long)k * NNODE + n) * D2 + c];
    atomicAdd(&g_emb[k * D2 + c], s * (1.0f / NNODE));
}

// ---------------- LSTM input projections: embs @ Wih^T ----------------
__global__ void k_xw(const float* __restrict__ Wih_f, const float* __restrict__ Wih_b) {
    int gid = blockIdx.x * 8 + (threadIdx.x >> 5);
    int lane = threadIdx.x & 31;
    int d = gid >> 13;
    int rem = gid & 8191;
    int k = rem >> 10;
    int g = rem & 1023;
    const float* Wih = d ? Wih_b : Wih_f;
    float s = 0.f;
    for (int j = lane; j < D2; j += 32)
        s += Wih[g * D2 + j] * g_emb[k * D2 + j];
    s = warp_sum(s);
    if (lane == 0) g_xw[gid] = s;
}

__global__ void k_whhT(const float* __restrict__ Whh_f, const float* __restrict__ Whh_b) {
    int idx = blockIdx.x * blockDim.x + threadIdx.x;
    if (idx >= 2 * 128 * 1024) return;
    int d = idx >> 17;
    int r = idx & ((1 << 17) - 1);
    int j2 = r >> 10;
    int t = r & 1023;
    const float* W = d ? Whh_b : Whh_f;
    g_whhT2[(((long)d * 128 + j2) << 10) + t] = make_float2(W[t * 256 + 2 * j2], W[t * 256 + 2 * j2 + 1]);
}

// ---------------- bidirectional LSTM with f32x2 inner product ----------------
__global__ __launch_bounds__(1024) void k_lstm(const float* __restrict__ bih_f, const float* __restrict__ bhh_f,
                                               const float* __restrict__ bih_b, const float* __restrict__ bhh_b,
                                               float* __restrict__ out) {
    int d = blockIdx.x;
    int t = threadIdx.x;
    __shared__ float2 h2[LH / 2];
    __shared__ float cc[LH], gbuf[4 * LH];
    if (t < LH / 2) h2[t] = make_float2(0.f, 0.f);
    if (t < LH) cc[t] = 0.f;
    const float* bih = d ? bih_b : bih_f;
    const float* bhh = d ? bhh_b : bhh_f;
    const unsigned long long* WT = (const unsigned long long*)(g_whhT2 + (long)d * 128 * 1024);
    const unsigned long long* hp = (const unsigned long long*)h2;
    float bsum = bih[t] + bhh[t];
    __syncthreads();
    for (int step = 0; step < KSNAP; step++) {
        int kk = d ? (KSNAP - 1 - step) : step;
        unsigned long long acc2 = 0ull;
#pragma unroll 8
        for (int j2 = 0; j2 < LH / 2; j2++) {
            unsigned long long w = WT[(long)j2 * 1024 + t];
            unsigned long long hh = hp[j2];
            FMA2(acc2, w, hh);
        }
        float lo, hi;
        unpack2(acc2, lo, hi);
        gbuf[t] = lo + hi + g_xw[((long)d * KSNAP + kk) * 1024 + t] + bsum;
        __syncthreads();
        if (t < LH) {
            float ig = 1.f / (1.f + expf(-gbuf[t]));
            float fg = 1.f / (1.f + expf(-gbuf[LH + t]));
            float gg = tanhf(gbuf[2 * LH + t]);
            float og = 1.f / (1.f + expf(-gbuf[3 * LH + t]));
            float cn = fg * cc[t] + ig * gg;
            cc[t] = cn;
            ((float*)h2)[t] = og * tanhf(cn);
        }
        __syncthreads();
    }
    if (t < LH) out[d * LH + t] = ((float*)h2)[t];
}

// ---------------- launch ----------------
extern "C" void kernel_launch(void* const* d_in, const int* in_sizes, int n_in,
                              void* d_out, int out_size) {
    const float* xs     = (const float*)d_in[0];
    const int*   ei     = (const int*)  d_in[1];
    const float* W1     = (const float*)d_in[2];
    const float* a_src1 = (const float*)d_in[3];
    const float* a_dst1 = (const float*)d_in[4];
    const float* b1     = (const float*)d_in[5];
    const float* W2     = (const float*)d_in[6];
    const float* a_src2 = (const float*)d_in[7];
    const float* a_dst2 = (const float*)d_in[8];
    const float* b2     = (const float*)d_in[9];
    const float* Wih_f  = (const float*)d_in[10];
    const float* Whh_f  = (const float*)d_in[11];
    const float* bih_f  = (const float*)d_in[12];
    const float* bhh_f  = (const float*)d_in[13];
    const float* Wih_b  = (const float*)d_in[14];
    const float* Whh_b  = (const float*)d_in[15];
    const float* bih_b  = (const float*)d_in[16];
    const float* bhh_b  = (const float*)d_in[17];
    float* out = (float*)d_out;

    k_zero<<<(KSNAP * NNODE + 255) / 256, 256>>>();
    k_count<<<(KSNAP * EPTOT + 255) / 256, 256>>>(ei);
    k_scan<<<KSNAP, 1024>>>();
    k_scatter<<<(KSNAP * EPTOT + 255) / 256, 256>>>(ei);

    dim3 gagg(NNODE / 8, KSNAP);

    // layer 1 (scalar form)
    k_prep<<<1, 256>>>(W1, a_src1, a_dst1);
    k_agg1<<<gagg, 256>>>(xs);

    // layer 2: fused GEMM (+ s-vector epilogue), then aggregation
    k_gemm<<<dim3((KSNAP * NNODE) / BM, D2 / BN), 256>>>(W2, W1, b1, a_src2, a_dst2);
    k_agg2<<<gagg, 256>>>(b2);

    // mean pool
    k_pool<<<dim3(32, KSNAP), 256>>>();

    // LSTM
    k_whhT<<<(2 * 128 * 1024 + 255) / 256, 256>>>(Whh_f, Whh_b);
    k_xw<<<2048, 256>>>(Wih_f, Wih_b);
    k_lstm<<<2, 1024>>>(bih_f, bhh_f, bih_b, bhh_b, out);
}